// round 11
// baseline (speedup 1.0000x reference)
#include <cuda_runtime.h>

typedef unsigned long long u64;

#define HH    56
#define WW    56
#define CIN   64
#define COUT  64
#define TILE  8
#define NB    16
#define QSPLIT 8                       // one 8-ci chunk per CTA
#define PIX   (NB * COUT * HH * WW)    // floats per partial = 3,211,264

// partial[q][n][co][h][w]; 8 x 12.85 MB = 102.8 MB static scratch
__device__ float g_partial[QSPLIT * PIX];

__device__ __forceinline__ u64 addx2(u64 a, u64 b) {
    u64 r; asm("add.rn.f32x2 %0, %1, %2;" : "=l"(r) : "l"(a), "l"(b)); return r;
}
__device__ __forceinline__ u64 pack2(float lo, float hi) {
    u64 r; asm("mov.b64 %0, {%1, %2};" : "=l"(r) : "f"(lo), "f"(hi)); return r;
}
__device__ __forceinline__ void unpack2(u64 v, float& lo, float& hi) {
    asm("mov.b64 {%0, %1}, %2;" : "=f"(lo), "=f"(hi) : "l"(v));
}
__device__ __forceinline__ u64 abs2(u64 v) {   // 2x LOP3 (alu pipe)
    return v & 0x7FFFFFFF7FFFFFFFull;
}

// x pre-paired stride-4: sxp[ci][row][t] = (x[t], x[t+4]), t=0..5 (48B rows)
__shared__ __align__(16) u64 sxp[8][10][6];     // 3.84 KB
__shared__ __align__(16) u64 swd[8][9][64];     // dup (-w,-w) pairs, 36.9 KB

// CTA: one (n, ci-eighth), one 8x8 tile, ALL 64 output channels.
// 128 threads: py = tid&7, cg = tid>>3 -> 4 channels each.
__global__ void __launch_bounds__(128, 5)
adder2d_partial_kernel(const float* __restrict__ x,
                       const float* __restrict__ w)
{
    const int tid  = threadIdx.x;
    const int py   = tid & 7;
    const int co4  = (tid >> 3) * 4;

    const int tx0 = blockIdx.x * TILE;
    const int ty0 = blockIdx.y * TILE;
    const int n   = blockIdx.z >> 3;
    const int c8  = blockIdx.z & 7;      // this CTA's ci chunk

    const float* xn = x + (size_t)n * CIN * HH * WW;

    // ---- stage x chunk: 8 ci x 10 rows x 6 stride-4 pairs ----
    #pragma unroll
    for (int it = 0; it < 4; ++it) {              // 480 / 128
        int idx = it * 128 + tid;
        if (idx < 480) {
            int ci_l = idx / 60;
            int r    = idx - ci_l * 60;
            int row  = r / 6;
            int t    = r - row * 6;
            int gy   = ty0 + row - 1;
            int gx0  = tx0 + t - 1;
            float lo = 0.0f, hi = 0.0f;
            if ((unsigned)gy < (unsigned)HH) {
                const float* base = &xn[((c8 * 8 + ci_l) * HH + gy) * WW];
                if ((unsigned)gx0 < (unsigned)WW)       lo = base[gx0];
                if ((unsigned)(gx0 + 4) < (unsigned)WW) hi = base[gx0 + 4];
            }
            sxp[ci_l][row][t] = pack2(lo, hi);
        }
    }
    // ---- stage weights: 8 ci x 9 k x 64 co, negated + duplicated ----
    #pragma unroll
    for (int it = 0; it < 36; ++it) {             // 4608 / 128
        int idx  = it * 128 + tid;
        int co   = idx & 63;
        int rest = idx >> 6;                      // 0..71
        int k    = rest % 9;
        int ci_l = rest / 9;
        float wv = -w[(co * CIN + c8 * 8 + ci_l) * 9 + k];
        swd[ci_l][k][co] = pack2(wv, wv);
    }
    __syncthreads();

    u64 acc[4][4];
    #pragma unroll
    for (int c = 0; c < 4; ++c)
        #pragma unroll
        for (int p = 0; p < 4; ++p) acc[c][p] = 0ull;

    for (int ci_l = 0; ci_l < 8; ++ci_l) {
        #pragma unroll
        for (int kh = 0; kh < 3; ++kh) {
            const ulonglong2* xp = (const ulonglong2*)&sxp[ci_l][py + kh][0];
            ulonglong2 a = xp[0], m = xp[1], e = xp[2];
            u64 x0 = a.x, x1 = a.y, x2 = m.x, x3 = m.y, x4 = e.x, x5 = e.y;

            #pragma unroll
            for (int kw = 0; kw < 3; ++kw) {
                u64 p0 = (kw == 0) ? x0 : (kw == 1) ? x1 : x2;
                u64 p1 = (kw == 0) ? x1 : (kw == 1) ? x2 : x3;
                u64 p2 = (kw == 0) ? x2 : (kw == 1) ? x3 : x4;
                u64 p3 = (kw == 0) ? x3 : (kw == 1) ? x4 : x5;
                const u64* wrow = &swd[ci_l][kh * 3 + kw][co4];
                ulonglong2 wA = *(const ulonglong2*)(wrow);
                ulonglong2 wB = *(const ulonglong2*)(wrow + 2);
                acc[0][0] = addx2(acc[0][0], abs2(addx2(p0, wA.x)));
                acc[0][1] = addx2(acc[0][1], abs2(addx2(p1, wA.x)));
                acc[0][2] = addx2(acc[0][2], abs2(addx2(p2, wA.x)));
                acc[0][3] = addx2(acc[0][3], abs2(addx2(p3, wA.x)));
                acc[1][0] = addx2(acc[1][0], abs2(addx2(p0, wA.y)));
                acc[1][1] = addx2(acc[1][1], abs2(addx2(p1, wA.y)));
                acc[1][2] = addx2(acc[1][2], abs2(addx2(p2, wA.y)));
                acc[1][3] = addx2(acc[1][3], abs2(addx2(p3, wA.y)));
                acc[2][0] = addx2(acc[2][0], abs2(addx2(p0, wB.x)));
                acc[2][1] = addx2(acc[2][1], abs2(addx2(p1, wB.x)));
                acc[2][2] = addx2(acc[2][2], abs2(addx2(p2, wB.x)));
                acc[2][3] = addx2(acc[2][3], abs2(addx2(p3, wB.x)));
                acc[3][0] = addx2(acc[3][0], abs2(addx2(p0, wB.y)));
                acc[3][1] = addx2(acc[3][1], abs2(addx2(p1, wB.y)));
                acc[3][2] = addx2(acc[3][2], abs2(addx2(p2, wB.y)));
                acc[3][3] = addx2(acc[3][3], abs2(addx2(p3, wB.y)));
            }
        }
    }

    // ---- epilogue: positive partial sums -> scratch[q] ----
    #pragma unroll
    for (int c = 0; c < 4; ++c) {
        float f[8];
        #pragma unroll
        for (int j = 0; j < 4; ++j) {
            float lo, hi;
            unpack2(acc[c][j], lo, hi);
            f[j]     = lo;
            f[j + 4] = hi;
        }
        float* o = g_partial + (size_t)c8 * PIX
                 + (((size_t)n * COUT + co4 + c) * HH + (ty0 + py)) * WW + tx0;
        ((float4*)o)[0] = make_float4(f[0], f[1], f[2], f[3]);
        ((float4*)o)[1] = make_float4(f[4], f[5], f[6], f[7]);
    }
}

// out = -(sum of 8 partials), float4-vectorized, MLP=8
__global__ void __launch_bounds__(256)
adder2d_reduce_kernel(float* __restrict__ out)
{
    const size_t i = (size_t)blockIdx.x * 256 + threadIdx.x;   // float4 index
    const float4* p = (const float4*)g_partial;
    const size_t Q = PIX / 4;

    float4 v[QSPLIT];
    #pragma unroll
    for (int q = 0; q < QSPLIT; ++q) v[q] = p[i + (size_t)q * Q];

    float4 r;
    r.x = -(((v[0].x + v[1].x) + (v[2].x + v[3].x)) +
            ((v[4].x + v[5].x) + (v[6].x + v[7].x)));
    r.y = -(((v[0].y + v[1].y) + (v[2].y + v[3].y)) +
            ((v[4].y + v[5].y) + (v[6].y + v[7].y)));
    r.z = -(((v[0].z + v[1].z) + (v[2].z + v[3].z)) +
            ((v[4].z + v[5].z) + (v[6].z + v[7].z)));
    r.w = -(((v[0].w + v[1].w) + (v[2].w + v[3].w)) +
            ((v[4].w + v[5].w) + (v[6].w + v[7].w)));
    ((float4*)out)[i] = r;
}

extern "C" void kernel_launch(void* const* d_in, const int* in_sizes, int n_in,
                              void* d_out, int out_size)
{
    const float* x = (const float*)d_in[0];
    const float* w = (const float*)d_in[1];
    float* out     = (float*)d_out;

    dim3 grid(WW / TILE, HH / TILE, NB * QSPLIT);   // 7 x 7 x 128 = 6272 CTAs
    adder2d_partial_kernel<<<grid, 128>>>(x, w);

    adder2d_reduce_kernel<<<PIX / 4 / 256, 256>>>(out);   // 3136 blocks
}

// round 12
// speedup vs baseline: 1.2023x; 1.2023x over previous
#include <cuda_runtime.h>

#define HH    56
#define WW    56
#define CIN   64
#define COUT  64
#define TILE  8
#define NB    16
#define QSPLIT 4                       // ci quarters (2 chunks per CTA)
#define PIX   (NB * COUT * HH * WW)    // floats per partial = 12,845,056

// partial[q][n][co][h][w], NEGATIVE sums; 4 x 12.85M floats = 51.4 MB scratch
__device__ float g_partial[QSPLIT * PIX];

// CTA: one (n, ci-quarter), one 8x8 tile, ALL 64 output channels.
// 128 threads: py = tid&7 (tile row), cg = tid>>3 -> 4 channels each.
// Thread: 8 px x 4 channels, scalar fp32 accumulators (32 regs).
// Scalar FADD formulation: acc -= fabsf(x - w)  -> 2 FADD/term, fma pipe only,
// no duplicated weights -> smem 22.3 KB -> 7 CTAs/SM -> 3136/1036 = 3.03 waves.
__global__ void __launch_bounds__(128, 7)
adder2d_partial_kernel(const float* __restrict__ x,
                       const float* __restrict__ w)
{
    __shared__ __align__(16) float sx[8][10][12];   // 8 ci x 10 rows x 12 cols (pad), 3.84 KB
    __shared__ __align__(16) float swn[8][9][64];   // plain weights [ci][k][co], 18.4 KB

    const int tid  = threadIdx.x;
    const int py   = tid & 7;
    const int co4  = (tid >> 3) * 4;

    const int tx0 = blockIdx.x * TILE;
    const int ty0 = blockIdx.y * TILE;
    const int n   = blockIdx.z >> 2;
    const int q   = blockIdx.z & 3;      // ci quarter: chunks 2q, 2q+1

    const float* xn = x + (size_t)n * CIN * HH * WW;

    float acc[4][8];
    #pragma unroll
    for (int c = 0; c < 4; ++c)
        #pragma unroll
        for (int p = 0; p < 8; ++p) acc[c][p] = 0.0f;

    for (int cc = 0; cc < 2; ++cc) {
        const int c8 = q * 2 + cc;
        __syncthreads();   // previous chunk's readers done

        // ---- stage x chunk: 8 ci x 10 rows x 12 cols (cols 10,11 + halo zero) ----
        #pragma unroll
        for (int it = 0; it < 8; ++it) {              // 960 / 128 = 7.5
            int idx = it * 128 + tid;
            if (idx < 960) {
                int ci_l = idx / 120;
                int r    = idx - ci_l * 120;
                int row  = r / 12;
                int col  = r - row * 12;
                int gy   = ty0 + row - 1;
                int gx   = tx0 + col - 1;
                float v  = 0.0f;
                if (col < 10 && (unsigned)gy < (unsigned)HH && (unsigned)gx < (unsigned)WW)
                    v = xn[((c8 * 8 + ci_l) * HH + gy) * WW + gx];
                sx[ci_l][row][col] = v;
            }
        }
        // ---- stage weights: 8 ci x 9 k x 64 co, plain copy ----
        #pragma unroll
        for (int it = 0; it < 36; ++it) {             // 4608 / 128
            int idx  = it * 128 + tid;
            int co   = idx & 63;
            int rest = idx >> 6;                      // 0..71
            int k    = rest % 9;
            int ci_l = rest / 9;
            swn[ci_l][k][co] = w[(co * CIN + c8 * 8 + ci_l) * 9 + k];
        }
        __syncthreads();

        // ---- compute: per (ci,kh): 3 x-LDS.128 + 3 x (1 w-LDS.128 + 64 FADD) ----
        for (int ci_l = 0; ci_l < 8; ++ci_l) {
            #pragma unroll
            for (int kh = 0; kh < 3; ++kh) {
                const float4* rp = (const float4*)&sx[ci_l][py + kh][0];
                float4 a = rp[0], b = rp[1], e = rp[2];
                float xr[12] = {a.x, a.y, a.z, a.w, b.x, b.y, b.z, b.w,
                                e.x, e.y, e.z, e.w};

                #pragma unroll
                for (int kw = 0; kw < 3; ++kw) {
                    float4 w4 = *(const float4*)&swn[ci_l][kh * 3 + kw][co4];
                    #pragma unroll
                    for (int px = 0; px < 8; ++px) {
                        float xv = xr[px + kw];
                        acc[0][px] -= fabsf(xv - w4.x);   // FADD + FADD(-|.|)
                        acc[1][px] -= fabsf(xv - w4.y);
                        acc[2][px] -= fabsf(xv - w4.z);
                        acc[3][px] -= fabsf(xv - w4.w);
                    }
                }
            }
        }
    }

    // ---- epilogue: negative partial sums -> scratch[q] ----
    #pragma unroll
    for (int c = 0; c < 4; ++c) {
        float* o = g_partial + (size_t)q * PIX
                 + (((size_t)n * COUT + co4 + c) * HH + (ty0 + py)) * WW + tx0;
        ((float4*)o)[0] = make_float4(acc[c][0], acc[c][1], acc[c][2], acc[c][3]);
        ((float4*)o)[1] = make_float4(acc[c][4], acc[c][5], acc[c][6], acc[c][7]);
    }
}

// out = p0 + p1 + p2 + p3 (partials already negative), float4-vectorized
__global__ void __launch_bounds__(256)
adder2d_reduce_kernel(float* __restrict__ out)
{
    const size_t i = (size_t)blockIdx.x * 256 + threadIdx.x;   // float4 index
    const float4* p = (const float4*)g_partial;
    const size_t Q = PIX / 4;                                   // 3,211,264

    float4 a = p[i], b = p[i + Q], c = p[i + 2 * Q], d = p[i + 3 * Q];
    float4 r;
    r.x = (a.x + b.x) + (c.x + d.x);
    r.y = (a.y + b.y) + (c.y + d.y);
    r.z = (a.z + b.z) + (c.z + d.z);
    r.w = (a.w + b.w) + (c.w + d.w);
    ((float4*)out)[i] = r;
}

extern "C" void kernel_launch(void* const* d_in, const int* in_sizes, int n_in,
                              void* d_out, int out_size)
{
    const float* x = (const float*)d_in[0];
    const float* w = (const float*)d_in[1];
    float* out     = (float*)d_out;

    dim3 grid(WW / TILE, HH / TILE, NB * QSPLIT);   // 7 x 7 x 64 = 3136 CTAs
    adder2d_partial_kernel<<<grid, 128>>>(x, w);

    adder2d_reduce_kernel<<<PIX / 4 / 256, 256>>>(out);   // 12544 blocks
}

// round 13
// speedup vs baseline: 1.2040x; 1.0014x over previous
#include <cuda_runtime.h>

#define HH    56
#define WW    56
#define CIN   64
#define COUT  64
#define TILE  8
#define NB    16
#define QSPLIT 4                       // ci quarters (2 chunks per CTA)
#define PIX   (NB * COUT * HH * WW)    // floats per partial = 12,845,056

// partial[q][n][co][h][w], NEGATIVE sums; 4 x 12.85M floats = 51.4 MB scratch
__device__ float g_partial[QSPLIT * PIX];

// CTA: one (n, ci-quarter), one 8x8 tile, ALL 64 output channels.
// 128 threads: py = tid&7 (tile row), cg = tid>>3 -> 4 channels each.
// Thread: 8 px x 4 channels, scalar fp32 accumulators.
// Scalar FADD formulation: acc -= fabsf(x - w) -> 2 FADD/term at rt=1 (fma pipe).
// smem 22.3 KB, 64-reg cap -> 8 CTAs/SM -> 3136/1184 = 2.65 -> 3 waves (cap 88%).
__global__ void __launch_bounds__(128, 8)
adder2d_partial_kernel(const float* __restrict__ x,
                       const float* __restrict__ w)
{
    __shared__ __align__(16) float sx[8][10][12];   // 8 ci x 10 rows x 12 cols, 3.84 KB
    __shared__ __align__(16) float swn[8][9][64];   // weights [ci][k][co], 18.4 KB

    const int tid  = threadIdx.x;
    const int py   = tid & 7;
    const int co4  = (tid >> 3) * 4;

    const int tx0 = blockIdx.x * TILE;
    const int ty0 = blockIdx.y * TILE;
    const int n   = blockIdx.z >> 2;
    const int q   = blockIdx.z & 3;      // ci quarter: chunks 2q, 2q+1

    const float* xn = x + (size_t)n * CIN * HH * WW;

    float acc[4][8];
    #pragma unroll
    for (int c = 0; c < 4; ++c)
        #pragma unroll
        for (int p = 0; p < 8; ++p) acc[c][p] = 0.0f;

    for (int cc = 0; cc < 2; ++cc) {
        const int c8 = q * 2 + cc;
        __syncthreads();   // previous chunk's readers done

        // ---- stage x chunk: 8 ci x 10 rows x 12 cols (cols 10,11 + halo zero) ----
        #pragma unroll
        for (int it = 0; it < 8; ++it) {              // 960 / 128 = 7.5
            int idx = it * 128 + tid;
            if (idx < 960) {
                int ci_l = idx / 120;
                int r    = idx - ci_l * 120;
                int row  = r / 12;
                int col  = r - row * 12;
                int gy   = ty0 + row - 1;
                int gx   = tx0 + col - 1;
                float v  = 0.0f;
                if (col < 10 && (unsigned)gy < (unsigned)HH && (unsigned)gx < (unsigned)WW)
                    v = xn[((c8 * 8 + ci_l) * HH + gy) * WW + gx];
                sx[ci_l][row][col] = v;
            }
        }
        // ---- stage weights: 8 ci x 9 k x 64 co, plain copy ----
        #pragma unroll
        for (int it = 0; it < 36; ++it) {             // 4608 / 128
            int idx  = it * 128 + tid;
            int co   = idx & 63;
            int rest = idx >> 6;                      // 0..71
            int k    = rest % 9;
            int ci_l = rest / 9;
            swn[ci_l][k][co] = w[(co * CIN + c8 * 8 + ci_l) * 9 + k];
        }
        __syncthreads();

        // ---- compute: per (ci,kh): 3 x-LDS.128 + 3 x (1 w-LDS.128 + 64 FADD) ----
        for (int ci_l = 0; ci_l < 8; ++ci_l) {
            #pragma unroll
            for (int kh = 0; kh < 3; ++kh) {
                const float4* rp = (const float4*)&sx[ci_l][py + kh][0];
                float4 a = rp[0], b = rp[1], e = rp[2];
                float xr[12] = {a.x, a.y, a.z, a.w, b.x, b.y, b.z, b.w,
                                e.x, e.y, e.z, e.w};

                #pragma unroll
                for (int kw = 0; kw < 3; ++kw) {
                    float4 w4 = *(const float4*)&swn[ci_l][kh * 3 + kw][co4];
                    #pragma unroll
                    for (int px = 0; px < 8; ++px) {
                        float xv = xr[px + kw];
                        acc[0][px] -= fabsf(xv - w4.x);   // FADD + FADD(-|.|)
                        acc[1][px] -= fabsf(xv - w4.y);
                        acc[2][px] -= fabsf(xv - w4.z);
                        acc[3][px] -= fabsf(xv - w4.w);
                    }
                }
            }
        }
    }

    // ---- epilogue: negative partial sums -> scratch[q] ----
    #pragma unroll
    for (int c = 0; c < 4; ++c) {
        float* o = g_partial + (size_t)q * PIX
                 + (((size_t)n * COUT + co4 + c) * HH + (ty0 + py)) * WW + tx0;
        ((float4*)o)[0] = make_float4(acc[c][0], acc[c][1], acc[c][2], acc[c][3]);
        ((float4*)o)[1] = make_float4(acc[c][4], acc[c][5], acc[c][6], acc[c][7]);
    }
}

// out = p0 + p1 + p2 + p3 (partials already negative), float4-vectorized
__global__ void __launch_bounds__(256)
adder2d_reduce_kernel(float* __restrict__ out)
{
    const size_t i = (size_t)blockIdx.x * 256 + threadIdx.x;   // float4 index
    const float4* p = (const float4*)g_partial;
    const size_t Q = PIX / 4;                                   // 3,211,264

    float4 a = p[i], b = p[i + Q], c = p[i + 2 * Q], d = p[i + 3 * Q];
    float4 r;
    r.x = (a.x + b.x) + (c.x + d.x);
    r.y = (a.y + b.y) + (c.y + d.y);
    r.z = (a.z + b.z) + (c.z + d.z);
    r.w = (a.w + b.w) + (c.w + d.w);
    ((float4*)out)[i] = r;
}

extern "C" void kernel_launch(void* const* d_in, const int* in_sizes, int n_in,
                              void* d_out, int out_size)
{
    const float* x = (const float*)d_in[0];
    const float* w = (const float*)d_in[1];
    float* out     = (float*)d_out;

    dim3 grid(WW / TILE, HH / TILE, NB * QSPLIT);   // 7 x 7 x 64 = 3136 CTAs
    adder2d_partial_kernel<<<grid, 128>>>(x, w);

    adder2d_reduce_kernel<<<PIX / 4 / 256, 256>>>(out);   // 12544 blocks
}

// round 14
// speedup vs baseline: 1.2044x; 1.0003x over previous
#include <cuda_runtime.h>

typedef unsigned long long u64;

#define HH    56
#define WW    56
#define CIN   64
#define COUT  64
#define TILE  8
#define NB    16
#define QSPLIT 4                       // ci quarters (2 chunks per CTA)
#define PIX   (NB * COUT * HH * WW)    // floats per partial = 12,845,056

// partial[q][n][co][h][w], NEGATIVE sums; 51.4 MB static scratch
__device__ float g_partial[QSPLIT * PIX];

__device__ __forceinline__ u64 addx2(u64 a, u64 b) {
    u64 r; asm("add.rn.f32x2 %0, %1, %2;" : "=l"(r) : "l"(a), "l"(b)); return r;
}
__device__ __forceinline__ u64 pack2(float lo, float hi) {
    u64 r; asm("mov.b64 %0, {%1, %2};" : "=l"(r) : "f"(lo), "f"(hi)); return r;
}
__device__ __forceinline__ void unpack2(u64 v, float& lo, float& hi) {
    asm("mov.b64 {%0, %1}, %2;" : "=f"(lo), "=f"(hi) : "l"(v));   // virtual, free
}

// CTA: one (n, ci-quarter), one 8x8 tile, ALL 64 output channels.
// 128 threads: py = tid&7, cg = tid>>3 -> 4 channels each.
// Form I per 2 terms: 1 addx2 (packed diff, 2 fma-cyc) + 2 scalar FADD -|.|
// (2 fma-cyc each) -> 3 fma-cyc/term (vs 4 scalar), issue duty 50%.
__global__ void __launch_bounds__(128, 5)
adder2d_partial_kernel(const float* __restrict__ x,
                       const float* __restrict__ w)
{
    // x pre-paired stride-4: sxp[ci][row][t] = (x[t], x[t+4]), t=0..5
    __shared__ __align__(16) u64 sxp[8][10][6];     // 3.84 KB
    __shared__ __align__(16) u64 swd[8][9][64];     // dup (-w,-w) pairs, 36.9 KB

    const int tid  = threadIdx.x;
    const int py   = tid & 7;
    const int co4  = (tid >> 3) * 4;

    const int tx0 = blockIdx.x * TILE;
    const int ty0 = blockIdx.y * TILE;
    const int n   = blockIdx.z >> 2;
    const int q   = blockIdx.z & 3;      // ci quarter: chunks 2q, 2q+1

    const float* xn = x + (size_t)n * CIN * HH * WW;

    float acc[4][8];
    #pragma unroll
    for (int c = 0; c < 4; ++c)
        #pragma unroll
        for (int p = 0; p < 8; ++p) acc[c][p] = 0.0f;

    for (int cc = 0; cc < 2; ++cc) {
        const int c8 = q * 2 + cc;
        __syncthreads();   // previous chunk's readers done

        // ---- stage x chunk: 8 ci x 10 rows x 6 stride-4 pairs ----
        #pragma unroll
        for (int it = 0; it < 4; ++it) {              // 480 / 128
            int idx = it * 128 + tid;
            if (idx < 480) {
                int ci_l = idx / 60;
                int r    = idx - ci_l * 60;
                int row  = r / 6;
                int t    = r - row * 6;
                int gy   = ty0 + row - 1;
                int gx0  = tx0 + t - 1;
                float lo = 0.0f, hi = 0.0f;
                if ((unsigned)gy < (unsigned)HH) {
                    const float* base = &xn[((c8 * 8 + ci_l) * HH + gy) * WW];
                    if ((unsigned)gx0 < (unsigned)WW)       lo = base[gx0];
                    if ((unsigned)(gx0 + 4) < (unsigned)WW) hi = base[gx0 + 4];
                }
                sxp[ci_l][row][t] = pack2(lo, hi);
            }
        }
        // ---- stage weights: 8 ci x 9 k x 64 co, negated + duplicated ----
        #pragma unroll
        for (int it = 0; it < 36; ++it) {             // 4608 / 128
            int idx  = it * 128 + tid;
            int co   = idx & 63;
            int rest = idx >> 6;                      // 0..71
            int k    = rest % 9;
            int ci_l = rest / 9;
            float wv = -w[(co * CIN + c8 * 8 + ci_l) * 9 + k];
            swd[ci_l][k][co] = pack2(wv, wv);
        }
        __syncthreads();

        // ---- compute ----
        for (int ci_l = 0; ci_l < 8; ++ci_l) {
            #pragma unroll
            for (int kh = 0; kh < 3; ++kh) {
                const ulonglong2* xp = (const ulonglong2*)&sxp[ci_l][py + kh][0];
                ulonglong2 a = xp[0], m = xp[1], e = xp[2];   // 3x LDS.128
                u64 P[6] = {a.x, a.y, m.x, m.y, e.x, e.y};

                #pragma unroll
                for (int kw = 0; kw < 3; ++kw) {
                    const u64* wrow = &swd[ci_l][kh * 3 + kw][co4];
                    ulonglong2 wA = *(const ulonglong2*)(wrow);
                    ulonglong2 wB = *(const ulonglong2*)(wrow + 2);
                    u64 wd[4] = {wA.x, wA.y, wB.x, wB.y};

                    #pragma unroll
                    for (int c = 0; c < 4; ++c) {
                        #pragma unroll
                        for (int j = 0; j < 4; ++j) {
                            u64 d2 = addx2(P[j + kw], wd[c]);   // 2 diffs, 2 cyc
                            float lo, hi;
                            unpack2(d2, lo, hi);
                            acc[c][j]     -= fabsf(lo);   // FADD acc,acc,-|lo|
                            acc[c][j + 4] -= fabsf(hi);   // FADD acc,acc,-|hi|
                        }
                    }
                }
            }
        }
    }

    // ---- epilogue: negative partial sums -> scratch[q] ----
    #pragma unroll
    for (int c = 0; c < 4; ++c) {
        float* o = g_partial + (size_t)q * PIX
                 + (((size_t)n * COUT + co4 + c) * HH + (ty0 + py)) * WW + tx0;
        ((float4*)o)[0] = make_float4(acc[c][0], acc[c][1], acc[c][2], acc[c][3]);
        ((float4*)o)[1] = make_float4(acc[c][4], acc[c][5], acc[c][6], acc[c][7]);
    }
}

// out = p0 + p1 + p2 + p3 (partials already negative), float4-vectorized
__global__ void __launch_bounds__(256)
adder2d_reduce_kernel(float* __restrict__ out)
{
    const size_t i = (size_t)blockIdx.x * 256 + threadIdx.x;   // float4 index
    const float4* p = (const float4*)g_partial;
    const size_t Q = PIX / 4;                                   // 3,211,264

    float4 a = p[i], b = p[i + Q], c = p[i + 2 * Q], d = p[i + 3 * Q];
    float4 r;
    r.x = (a.x + b.x) + (c.x + d.x);
    r.y = (a.y + b.y) + (c.y + d.y);
    r.z = (a.z + b.z) + (c.z + d.z);
    r.w = (a.w + b.w) + (c.w + d.w);
    ((float4*)out)[i] = r;
}

extern "C" void kernel_launch(void* const* d_in, const int* in_sizes, int n_in,
                              void* d_out, int out_size)
{
    const float* x = (const float*)d_in[0];
    const float* w = (const float*)d_in[1];
    float* out     = (float*)d_out;

    dim3 grid(WW / TILE, HH / TILE, NB * QSPLIT);   // 7 x 7 x 64 = 3136 CTAs
    adder2d_partial_kernel<<<grid, 128>>>(x, w);

    adder2d_reduce_kernel<<<PIX / 4 / 256, 256>>>(out);   // 12544 blocks
}